// round 10
// baseline (speedup 1.0000x reference)
#include <cuda_runtime.h>

// Problem constants (fixed by the reference)
#define BATCH 16
#define MCTRL 64          // control points per dim
#define DEG   3           // degree P == Q
#define KLEN  68          // MCTRL + DEG + 1 knots
#define NSPAN 62          // KLEN - 2*DEG candidate spans
#define TPTS  256         // OUT_U == OUT_V
#define IPB   4           // output rows (i values) per block

// 32-lane inclusive scan via shfl
__device__ __forceinline__ float warp_iscan(float v, int lane) {
    #pragma unroll
    for (int off = 1; off < 32; off <<= 1) {
        const float t = __shfl_up_sync(0xffffffffu, v, off);
        if (lane >= off) v += t;
    }
    return v;
}

// ---------------------------------------------------------------------------
// Fused kernel. Block = (i-tile of IPB rows, batch b), 256 threads (one per j).
//   0) warp-0 shuffle scan of the 68 knots -> normalized U in smem
//      (Nv==Nu: the reference builds V from knot_u too, and u==v).
//   1) every thread: span via 2-round probe count (independent LDS) +
//      Cox-de Boor with HOISTED independent divisions (short FMA chain).
//      Threads whose j equals a row index of this tile PUBLISH their basis
//      as the row basis (row basis == column basis of the same index).
//   2) row blend straight from global (coalesced LDG.32, L2-resident ctrl).
//   3) per j, per k: out = sum_r wv[r]*blend[k][col0+r]  (4 LDS.128/output).
// ---------------------------------------------------------------------------
__global__ void __launch_bounds__(TPTS) fused_kernel(
    const float4* __restrict__ ctrl,     // [B][64][64] float4
    const float*  __restrict__ knot_u,   // [B][68]
    float*        __restrict__ out)      // [B][256][256][3]
{
    const int b  = blockIdx.y;
    const int i0 = blockIdx.x * IPB;
    const int j  = threadIdx.x;

    __shared__ float  U[KLEN];
    __shared__ float4 blend[IPB][MCTRL];      // 4 KB
    __shared__ float  wu_s [IPB][4];
    __shared__ int    row0_s[IPB];

    // --- Stage 0: warp-0 scan of knots + normalize ---
    if (j < 32) {
        const float* kb = knot_u + b * KLEN;
        float a0 = kb[j];
        float a1 = kb[j + 32];
        float a2 = (j < KLEN - 64) ? kb[j + 64] : 0.0f;
        const float k0 = __shfl_sync(0xffffffffu, a0, 0);  // knot[0]

        a0 = warp_iscan(a0, j);
        const float tot0 = __shfl_sync(0xffffffffu, a0, 31);
        a1 = warp_iscan(a1, j) + tot0;
        const float tot1 = __shfl_sync(0xffffffffu, a1, 31);
        a2 = warp_iscan(a2, j) + tot1;

        const float last = __shfl_sync(0xffffffffu, a2, KLEN - 64 - 1); // c[67]
        const float inv  = 1.0f / (last - k0);
        U[j]      = (a0 - k0) * inv;
        U[j + 32] = (a1 - k0) * inv;
        if (j < KLEN - 64) U[j + 64] = (a2 - k0) * inv;
    }
    __syncthreads();

    // --- Stage 1: per-thread basis (span + Cox-de Boor) ---
    // cand[s] = (tp - U[3+s] > 1e-8) ? (tp - U[3+s]) : 1.  d is strictly
    // decreasing in s, so argmin = LAST valid s = #{s in 1..61 : valid}.
    const float tp = 1e-5f + (float)j * ((1.0f - 2e-5f) / 255.0f);

    int span;
    {
        // round 1: coarse probes s = 8,16,...,56 (independent LDS)
        int c = 0;
        #pragma unroll
        for (int m = 1; m <= 7; m++)
            c += (tp - U[DEG + 8 * m] > 1e-8f) ? 1 : 0;
        const int b0 = 8 * c;
        // round 2: fine probes s = b0+1 .. b0+7 (independent LDS)
        int f = 0;
        #pragma unroll
        for (int m = 1; m <= 7; m++) {
            const int s = b0 + m;
            f += (s <= NSPAN - 1 && (tp - U[DEG + s] > 1e-8f)) ? 1 : 0;
        }
        span = b0 + f + DEG;
    }

    // Cox-de Boor deg-3: hoist the 6 independent divisions, then pure FMAs.
    float wv0, wv1, wv2, wv3;
    {
        const float um2 = U[span - 2], um1 = U[span - 1], u0 = U[span];
        const float u1  = U[span + 1], u2  = U[span + 2], u3 = U[span + 3];
        const float r1 = u1 - tp, r2 = u2 - tp, r3 = u3 - tp;
        const float l0 = tp - u0, l1 = tp - um1, l2 = tp - um2;
        // denominators exactly as reference: (K1 - tp) + (tp - K2)
        const float i10 = 1.0f / (r1 + l0);
        const float i20 = 1.0f / (r1 + l1);
        const float i21 = 1.0f / (r2 + l0);
        const float i30 = 1.0f / (r1 + l2);
        const float i31 = 1.0f / (r2 + l1);
        const float i32 = 1.0f / (r3 + l0);

        float N0 = 1.0f, N1, N2, N3, t, s;
        // k=1
        t = N0 * i10;  N0 = r1 * t;          s = l0 * t;  N1 = s;
        // k=2
        t = N0 * i20;  N0 = r1 * t;          s = l1 * t;
        t = N1 * i21;  N1 = fmaf(r2, t, s);  s = l0 * t;  N2 = s;
        // k=3
        t = N0 * i30;  N0 = r1 * t;          s = l2 * t;
        t = N1 * i31;  N1 = fmaf(r2, t, s);  s = l1 * t;
        t = N2 * i32;  N2 = fmaf(r3, t, s);  s = l0 * t;  N3 = s;
        wv0 = N0; wv1 = N1; wv2 = N2; wv3 = N3;
    }

    int col0 = span - DEG;
    col0 = col0 < 0 ? 0 : (col0 > MCTRL - 4 ? MCTRL - 4 : col0);

    // Publish row bases: row basis for i0+k == column basis of thread j==i0+k.
    if ((unsigned)(j - i0) < IPB) {
        const int k = j - i0;
        wu_s[k][0] = wv0; wu_s[k][1] = wv1;
        wu_s[k][2] = wv2; wu_s[k][3] = wv3;
        row0_s[k]  = col0;
    }
    __syncthreads();

    // --- Stage 2: row blends straight from global ---
    // thread j <-> (col = j>>2, comp = j&3); float offset col*4+comp == j,
    // so each row read is a fully-coalesced 128B warp transaction (L2 hit).
    {
        const float* cbase = (const float*)ctrl + (size_t)b * MCTRL * MCTRL * 4;
        #pragma unroll
        for (int k = 0; k < IPB; k++) {
            const float* rp = cbase + (size_t)row0_s[k] * (MCTRL * 4) + j;
            float acc;
            acc = wu_s[k][0] * rp[0];
            acc = fmaf(wu_s[k][1], rp[1 * MCTRL * 4], acc);
            acc = fmaf(wu_s[k][2], rp[2 * MCTRL * 4], acc);
            acc = fmaf(wu_s[k][3], rp[3 * MCTRL * 4], acc);
            ((float*)blend)[k * MCTRL * 4 + j] = acc;   // blend[k][col].comp
        }
    }
    __syncthreads();

    // --- Stage 3: column stencil + store (4 LDS.128 per output) ---
    #pragma unroll
    for (int k = 0; k < IPB; k++) {
        const float4 c0 = blend[k][col0 + 0];
        const float4 c1 = blend[k][col0 + 1];
        const float4 c2 = blend[k][col0 + 2];
        const float4 c3 = blend[k][col0 + 3];
        const float x =
            fmaf(wv0, c0.x, fmaf(wv1, c1.x, fmaf(wv2, c2.x, wv3 * c3.x)));
        const float y =
            fmaf(wv0, c0.y, fmaf(wv1, c1.y, fmaf(wv2, c2.y, wv3 * c3.y)));
        const float z =
            fmaf(wv0, c0.z, fmaf(wv1, c1.z, fmaf(wv2, c2.z, wv3 * c3.z)));

        const long long base =
            ((((long long)b * TPTS + (i0 + k)) * TPTS) + j) * 3;
        out[base + 0] = x;
        out[base + 1] = y;
        out[base + 2] = z;
    }
}

// ---------------------------------------------------------------------------
// Launch: single fused kernel (knot_v is unused — the reference builds V
// from knot_u as well).
// ---------------------------------------------------------------------------
extern "C" void kernel_launch(void* const* d_in, const int* in_sizes, int n_in,
                              void* d_out, int out_size) {
    const float* ctrl   = (const float*)d_in[0];   // [16,64,64,4] f32
    const float* knot_u = (const float*)d_in[1];   // [16,68] f32
    (void)in_sizes; (void)n_in; (void)out_size;

    fused_kernel<<<dim3(TPTS / IPB, BATCH), TPTS>>>(
        (const float4*)ctrl, knot_u, (float*)d_out);
}

// round 11
// speedup vs baseline: 1.3821x; 1.3821x over previous
#include <cuda_runtime.h>

// Problem constants (fixed by the reference)
#define BATCH 16
#define MCTRL 64          // control points per dim
#define DEG   3           // degree P == Q
#define KLEN  68          // MCTRL + DEG + 1 knots
#define NSPAN 62          // KLEN - 2*DEG candidate spans
#define TPTS  256         // OUT_U == OUT_V
#define IPB   8           // output rows (i values) per block
#define NWARP (TPTS / 32)

// ---------------------------------------------------------------------------
// Per-thread basis: binary-search span + Cox-de Boor (deg 3), the reference's
// arithmetic (fast division; error ~1e-7 vs 1e-3 tolerance).
// Span = argmin over cand[s] = (tp-U[3+s] > 1e-8) ? tp-U[3+s] : 1.
// U[3..64] strictly increasing -> d strictly decreasing -> minimum is the
// LAST s with d > 1e-8 -> 6-step binary search. s=0 always valid.
// ---------------------------------------------------------------------------
__device__ __forceinline__ void basis_at(const float* __restrict__ U,
                                         float tp, float N[DEG + 1], int& span)
{
    int lo = 0, hi = NSPAN - 1;
    #pragma unroll
    for (int it = 0; it < 6; it++) {           // ceil(log2(62)) = 6
        const int mid = (lo + hi + 1) >> 1;
        if (lo < hi) {
            if (tp - U[DEG + mid] > 1e-8f) lo = mid; else hi = mid - 1;
        }
    }
    span = lo + DEG;

    N[0] = 1.0f;
    #pragma unroll
    for (int k = 1; k <= DEG; k++) {
        float saved = 0.0f;
        #pragma unroll
        for (int r = 0; r < k; r++) {
            const float K1 = U[span + r + 1];
            const float K2 = U[span + 1 - k + r];
            const float temp = __fdividef(N[r], (K1 - tp) + (tp - K2));
            N[r] = saved + (K1 - tp) * temp;
            saved = (tp - K2) * temp;
        }
        N[k] = saved;
    }
}

// 32-lane inclusive scan via shfl
__device__ __forceinline__ float warp_iscan(float v, int lane) {
    #pragma unroll
    for (int off = 1; off < 32; off <<= 1) {
        const float t = __shfl_up_sync(0xffffffffu, v, off);
        if (lane >= off) v += t;
    }
    return v;
}

// ---------------------------------------------------------------------------
// Fused kernel (R9 structure). Block = (i-tile of IPB rows, batch b),
// 256 threads (one per j).
//   0) warp-0 shuffle scan of the 68 knots -> normalized U in smem
//      (Nv==Nu: the reference builds V from knot_u too, and u==v).
//   1) every thread computes its own column basis; threads j==i0+k PUBLISH
//      theirs as the row basis (row basis == column basis of same index).
//   2) row blend straight from global (coalesced LDG.32, L2-resident ctrl).
//   3) per j, per k: stencil (4 LDS.128), then warp-level smem repack so the
//      3 floats/thread go out as 3 fully-coalesced 128B STGs instead of
//      stride-3 stores (3x sector inflation removed).
// ---------------------------------------------------------------------------
__global__ void __launch_bounds__(TPTS) fused_kernel(
    const float4* __restrict__ ctrl,     // [B][64][64] float4
    const float*  __restrict__ knot_u,   // [B][68]
    float*        __restrict__ out)      // [B][256][256][3]
{
    const int b  = blockIdx.y;
    const int i0 = blockIdx.x * IPB;
    const int j  = threadIdx.x;

    __shared__ float  U[KLEN];
    __shared__ float4 blend[IPB][MCTRL];      // 8 KB
    __shared__ float  wu_s [IPB][4];
    __shared__ int    row0_s[IPB];
    __shared__ float  pack[NWARP][96];        // 3 KB store-repack buffers

    // --- Stage 0: warp-0 scan of knots + normalize ---
    if (j < 32) {
        const float* kb = knot_u + b * KLEN;
        float a0 = kb[j];
        float a1 = kb[j + 32];
        float a2 = (j < KLEN - 64) ? kb[j + 64] : 0.0f;
        const float k0 = __shfl_sync(0xffffffffu, a0, 0);  // knot[0]

        a0 = warp_iscan(a0, j);
        const float tot0 = __shfl_sync(0xffffffffu, a0, 31);
        a1 = warp_iscan(a1, j) + tot0;
        const float tot1 = __shfl_sync(0xffffffffu, a1, 31);
        a2 = warp_iscan(a2, j) + tot1;

        const float last = __shfl_sync(0xffffffffu, a2, KLEN - 64 - 1); // c[67]
        const float inv  = 1.0f / (last - k0);
        U[j]      = (a0 - k0) * inv;
        U[j + 32] = (a1 - k0) * inv;
        if (j < KLEN - 64) U[j + 64] = (a2 - k0) * inv;
    }
    __syncthreads();

    // --- Stage 1: per-thread column basis; publish row bases ---
    const float step = (1.0f - 2e-5f) / 255.0f;

    float wv[DEG + 1];
    int   spanj;
    basis_at(U, 1e-5f + (float)j * step, wv, spanj);
    int col0 = spanj - DEG;
    col0 = col0 < 0 ? 0 : (col0 > MCTRL - 4 ? MCTRL - 4 : col0);

    if ((unsigned)(j - i0) < IPB) {            // thread j == i0+k
        const int k = j - i0;
        wu_s[k][0] = wv[0]; wu_s[k][1] = wv[1];
        wu_s[k][2] = wv[2]; wu_s[k][3] = wv[3];
        row0_s[k]  = col0;
    }
    __syncthreads();

    // --- Stage 2: row blends straight from global ---
    // thread j <-> (col = j>>2, comp = j&3); float offset col*4+comp == j,
    // so each row read is a fully-coalesced 128B warp transaction (L2 hit).
    {
        const float* cbase = (const float*)ctrl + b * (MCTRL * MCTRL * 4);
        #pragma unroll
        for (int k = 0; k < IPB; k++) {
            const float* rp = cbase + row0_s[k] * (MCTRL * 4) + j;
            float acc;
            acc = wu_s[k][0] * rp[0];
            acc = fmaf(wu_s[k][1], rp[1 * MCTRL * 4], acc);
            acc = fmaf(wu_s[k][2], rp[2 * MCTRL * 4], acc);
            acc = fmaf(wu_s[k][3], rp[3 * MCTRL * 4], acc);
            ((float*)blend)[k * MCTRL * 4 + j] = acc;   // blend[k][col].comp
        }
    }
    __syncthreads();

    // --- Stage 3: column stencil + repacked coalesced stores ---
    const int warp = j >> 5;
    const int lane = j & 31;
    float* pw = pack[warp];
    // warp's 32 columns are j0..j0+31 -> 96 consecutive output floats
    const int wbase = warp * 96;

    #pragma unroll
    for (int k = 0; k < IPB; k++) {
        const float4 c0 = blend[k][col0 + 0];
        const float4 c1 = blend[k][col0 + 1];
        const float4 c2 = blend[k][col0 + 2];
        const float4 c3 = blend[k][col0 + 3];
        const float x =
            fmaf(wv[0], c0.x, fmaf(wv[1], c1.x, fmaf(wv[2], c2.x, wv[3] * c3.x)));
        const float y =
            fmaf(wv[0], c0.y, fmaf(wv[1], c1.y, fmaf(wv[2], c2.y, wv[3] * c3.y)));
        const float z =
            fmaf(wv[0], c0.z, fmaf(wv[1], c1.z, fmaf(wv[2], c2.z, wv[3] * c3.z)));

        // stride-3 STS: banks 3*lane+c mod 32 -> permutation, conflict-free
        __syncwarp();
        pw[3 * lane + 0] = x;
        pw[3 * lane + 1] = y;
        pw[3 * lane + 2] = z;
        __syncwarp();

        // 3 fully-coalesced 128B stores (32-bit indexing: max idx < 2^22)
        const int rowbase = (b * TPTS + i0 + k) * (TPTS * 3) + wbase;
        out[rowbase + lane]      = pw[lane];
        out[rowbase + lane + 32] = pw[lane + 32];
        out[rowbase + lane + 64] = pw[lane + 64];
    }
}

// ---------------------------------------------------------------------------
// Launch: single fused kernel (knot_v is unused — the reference builds V
// from knot_u as well).
// ---------------------------------------------------------------------------
extern "C" void kernel_launch(void* const* d_in, const int* in_sizes, int n_in,
                              void* d_out, int out_size) {
    const float* ctrl   = (const float*)d_in[0];   // [16,64,64,4] f32
    const float* knot_u = (const float*)d_in[1];   // [16,68] f32
    (void)in_sizes; (void)n_in; (void)out_size;

    fused_kernel<<<dim3(TPTS / IPB, BATCH), TPTS>>>(
        (const float4*)ctrl, knot_u, (float*)d_out);
}